// round 16
// baseline (speedup 1.0000x reference)
#include <cuda_runtime.h>
#include <cuda_fp16.h>
#include <cstdint>

#define M_TOTAL 12608   // 64*197 (divisible by 64 -> no M guards)
#define K_DIM   768
#define R_DIM   192
#define BM      64
#define BN      192
#define BK      64      // fp16 elems per chunk = 128B row
#define NCHUNK  12
#define A_BYTES (BM * 128)            // 8192
#define B_BYTES (BN * 128)            // 24576
#define STAGE   (A_BYTES + B_BYTES)   // 32768
#define NSTAGE  2
#define SMEM_DYN (NSTAGE * STAGE + 1024)   // ~66KB -> 3 CTA/SM

#define SWZ(o) ((o) ^ (((o) >> 3) & 0x70))

// fp16 scratch (allocation-free __device__ globals)
__device__ __half g_Xh[(size_t)M_TOTAL * K_DIM];     // [M,K] row-major
__device__ __half g_Wh[(size_t)3 * R_DIM * K_DIM];   // [3][N=192][K=768] K-major

// ---------------- PTX helpers ----------------
__device__ __forceinline__ uint32_t smem_u32(const void* p) {
    uint32_t a;
    asm("{ .reg .u64 t; cvta.to.shared.u64 t, %1; cvt.u32.u64 %0, t; }" : "=r"(a) : "l"(p));
    return a;
}
__device__ __forceinline__ void cp16(uint32_t dst, const void* src) {
    asm volatile("cp.async.cg.shared.global [%0], [%1], 16;" :: "r"(dst), "l"(src) : "memory");
}
#define CP_COMMIT() asm volatile("cp.async.commit_group;" ::: "memory")
#define CP_WAIT0()  asm volatile("cp.async.wait_group 0;" ::: "memory")
#define CP_WAIT1()  asm volatile("cp.async.wait_group 1;" ::: "memory")

__device__ __forceinline__ void ldsm4(uint32_t* r, uint32_t addr) {
    asm volatile("ldmatrix.sync.aligned.m8n8.x4.shared.b16 {%0,%1,%2,%3}, [%4];"
                 : "=r"(r[0]), "=r"(r[1]), "=r"(r[2]), "=r"(r[3]) : "r"(addr));
}
__device__ __forceinline__ void mma16816(float* c, const uint32_t* a, const uint32_t* b) {
    asm volatile(
        "mma.sync.aligned.m16n8k16.row.col.f32.f16.f16.f32 "
        "{%0,%1,%2,%3}, {%4,%5,%6,%7}, {%8,%9}, {%0,%1,%2,%3};"
        : "+f"(c[0]), "+f"(c[1]), "+f"(c[2]), "+f"(c[3])
        : "r"(a[0]), "r"(a[1]), "r"(a[2]), "r"(a[3]), "r"(b[0]), "r"(b[1]));
}
__device__ __forceinline__ float gelu_exact(float x) {
    return 0.5f * x * (1.0f + erff(x * 0.70710678118654752f));
}

// ---------------- fused convert prepass (X stream + W smem-tile transpose) ----------------
#define XBLK 1182   // (12608*768/8 uint4) / (4*256)
#define WBLK 432    // 3 matrices * (768/32)*(192/32) tiles
__global__ __launch_bounds__(256, 4)
void cvt_xw_kernel(const float4* __restrict__ X,
                   const float* __restrict__ Wq, const float* __restrict__ Wk,
                   const float* __restrict__ Wv, uint4* __restrict__ xh_out) {
    __shared__ float s[32][33];      // padded transpose tile (W branch only)

    if (blockIdx.x < XBLK) {
        const int n_u4 = (M_TOTAL * K_DIM) / 8;              // 1210368
        const int t = blockIdx.x * blockDim.x + threadIdx.x;
        const int stride = XBLK * 256;
        float4 v[8];
        #pragma unroll
        for (int u = 0; u < 4; ++u) {
            int i = t + u * stride;
            if (i < n_u4) {
                v[2 * u + 0] = __ldcs(&X[2 * i + 0]);   // X is single-use: stream it
                v[2 * u + 1] = __ldcs(&X[2 * i + 1]);
            }
        }
        #pragma unroll
        for (int u = 0; u < 4; ++u) {
            int i = t + u * stride;
            if (i < n_u4) {
                __half2 h0 = __floats2half2_rn(v[2*u].x,   v[2*u].y);
                __half2 h1 = __floats2half2_rn(v[2*u].z,   v[2*u].w);
                __half2 h2 = __floats2half2_rn(v[2*u+1].x, v[2*u+1].y);
                __half2 h3 = __floats2half2_rn(v[2*u+1].z, v[2*u+1].w);
                uint4 o;
                o.x = *reinterpret_cast<uint32_t*>(&h0);
                o.y = *reinterpret_cast<uint32_t*>(&h1);
                o.z = *reinterpret_cast<uint32_t*>(&h2);
                o.w = *reinterpret_cast<uint32_t*>(&h3);
                xh_out[i] = o;       // g_Xh re-read by GEMM: default (L2) hint
            }
        }
    } else {
        // W transpose: [K=768, N=192] fp32 -> [N, K] fp16, 32x32 smem tiles.
        const int bid2 = blockIdx.x - XBLK;      // 0..431
        const int w    = bid2 / 144;             // matrix 0..2
        const int t2   = bid2 - w * 144;
        const int kt   = t2 / 6;                 // 0..23
        const int nt   = t2 - kt * 6;            // 0..5
        const int k0   = kt * 32;
        const int n0   = nt * 32;
        const int tx   = threadIdx.x & 31;
        const int ty   = threadIdx.x >> 5;       // 0..7
        const float* W = (w == 0) ? Wq : (w == 1) ? Wk : Wv;

        #pragma unroll
        for (int r = 0; r < 4; ++r)
            s[ty + 8 * r][tx] = W[(size_t)(k0 + ty + 8 * r) * R_DIM + n0 + tx];
        __syncthreads();
        __half* out = g_Wh + (size_t)w * R_DIM * K_DIM;
        #pragma unroll
        for (int r = 0; r < 4; ++r)
            out[(size_t)(n0 + ty + 8 * r) * K_DIM + k0 + tx] =
                __float2half_rn(s[tx][ty + 8 * r]);
    }
}

// ---------------- chunk loader (cp.async, swizzled 128B rows) ----------------
__device__ __forceinline__ void load_chunk(int c, uint32_t st, const __half* Asrc,
                                           const __half* Bsrc, int tid) {
    // A: 64 rows x 8 16B-chunks = 512 -> 4 per thread (128 threads)
    #pragma unroll
    for (int u = 0; u < 4; ++u) {
        int idx = tid + u * 128;
        int row = idx >> 3;
        int j   = idx & 7;
        cp16(st + SWZ(row * 128 + j * 16),
             Asrc + (size_t)row * K_DIM + c * BK + j * 8);
    }
    // B: 192 rows x 8 = 1536 -> 12 per thread
    #pragma unroll
    for (int u = 0; u < 12; ++u) {
        int idx = tid + u * 128;
        int row = idx >> 3;
        int j   = idx & 7;
        cp16(st + A_BYTES + SWZ(row * 128 + j * 16),
             Bsrc + (size_t)row * K_DIM + c * BK + j * 8);
    }
}

// ---------------- GEMM: CTA 64x192, 4 warps (1x4), 2-stage, occ 3, frag-pipelined ----------------
__global__ __launch_bounds__(128, 3)
void qkv_mma_kernel(float* __restrict__ Out) {
    extern __shared__ char dynsm[];
    const int tid  = threadIdx.x;
    const int wid  = tid >> 5;                // 0..3
    const int lane = tid & 31;
    const int nb   = blockIdx.x;              // 0..2 -> q/k/v
    const int bm   = blockIdx.y * BM;

    const int warp_n = wid * 48;

    uint32_t base = (smem_u32(dynsm) + 1023u) & ~1023u;

    const __half* Asrc = g_Xh + (size_t)bm * K_DIM;
    const __half* Bsrc = g_Wh + (size_t)nb * R_DIM * K_DIM;

    // per-lane ldmatrix offsets
    const int a_row_off = lane & 15;
    const int a_k_off   = (lane >> 4) * 16;
    const int b_n_off   = (lane & 7) | ((lane & 16) >> 1);
    const int b_k_off   = (lane & 8) ? 16 : 0;

    float acc[4][6][4];
    #pragma unroll
    for (int i = 0; i < 4; ++i)
        #pragma unroll
        for (int j = 0; j < 6; ++j)
            #pragma unroll
            for (int q = 0; q < 4; ++q) acc[i][j][q] = 0.0f;

    uint32_t afrag[2][4][4], bfrag[2][3][4];

    // prologue: chunks 0,1 in flight (2-stage ring)
    load_chunk(0, base, Asrc, Bsrc, tid);          CP_COMMIT();
    load_chunk(1, base + STAGE, Asrc, Bsrc, tid);  CP_COMMIT();

    for (int j = 0; j < NCHUNK; ++j) {
        if (j + 1 < NCHUNK) { CP_WAIT1(); } else { CP_WAIT0(); }
        __syncthreads();                 // chunk j resident in stage j%2

        const uint32_t a_sm = base + (j & 1) * STAGE;
        const uint32_t b_sm = a_sm + A_BYTES;

        // preload ks=0 fragments
        #pragma unroll
        for (int mf = 0; mf < 4; ++mf)
            ldsm4(afrag[0][mf], a_sm + SWZ((mf * 16 + a_row_off) * 128 + a_k_off));
        #pragma unroll
        for (int nf2 = 0; nf2 < 3; ++nf2)
            ldsm4(bfrag[0][nf2], b_sm + SWZ((warp_n + nf2 * 16 + b_n_off) * 128 + b_k_off));

        #pragma unroll
        for (int ks = 0; ks < 4; ++ks) {
            const int cur = ks & 1;
            if (ks < 3) {   // prefetch ks+1 frags while MMAs of ks run
                const int nxt = cur ^ 1;
                #pragma unroll
                for (int mf = 0; mf < 4; ++mf)
                    ldsm4(afrag[nxt][mf],
                          a_sm + SWZ((mf * 16 + a_row_off) * 128 + (ks + 1) * 32 + a_k_off));
                #pragma unroll
                for (int nf2 = 0; nf2 < 3; ++nf2)
                    ldsm4(bfrag[nxt][nf2],
                          b_sm + SWZ((warp_n + nf2 * 16 + b_n_off) * 128 + (ks + 1) * 32 + b_k_off));
            }
            #pragma unroll
            for (int mf = 0; mf < 4; ++mf)
                #pragma unroll
                for (int nf = 0; nf < 6; ++nf)
                    mma16816(acc[mf][nf], afrag[cur][mf], &bfrag[cur][nf >> 1][(nf & 1) * 2]);
        }

        __syncthreads();                 // all warps done reading stage j%2
        if (j + 2 < NCHUNK) {
            load_chunk(j + 2, base + (j & 1) * STAGE, Asrc, Bsrc, tid);
            CP_COMMIT();
        }
    }

    // ---- epilogue: GELU + float2 stores (no M guards: 12608 % 64 == 0)
    float* __restrict__ outbase =
        Out + (size_t)nb * (size_t)M_TOTAL * R_DIM + warp_n;
    const int rbase = bm + (lane >> 2);
    const int cbase = (lane & 3) * 2;
    #pragma unroll
    for (int mf = 0; mf < 4; ++mf) {
        #pragma unroll
        for (int half = 0; half < 2; ++half) {
            int row = rbase + mf * 16 + half * 8;
            float* op = outbase + (size_t)row * R_DIM + cbase;
            #pragma unroll
            for (int nf = 0; nf < 6; ++nf) {
                float2 o;
                o.x = gelu_exact(acc[mf][nf][half * 2 + 0]);
                o.y = gelu_exact(acc[mf][nf][half * 2 + 1]);
                *reinterpret_cast<float2*>(op + nf * 8) = o;
            }
        }
    }
}

extern "C" void kernel_launch(void* const* d_in, const int* in_sizes, int n_in,
                              void* d_out, int out_size) {
    const float* X  = (const float*)d_in[0];  // [64,197,768]
    const float* Wq = (const float*)d_in[1];  // [768,192]
    const float* Wk = (const float*)d_in[2];
    const float* Wv = (const float*)d_in[3];
    float* Out = (float*)d_out;

    cudaFuncSetAttribute(qkv_mma_kernel, cudaFuncAttributeMaxDynamicSharedMemorySize, SMEM_DYN);

    __half* xh_ptr = nullptr;
    cudaGetSymbolAddress((void**)&xh_ptr, g_Xh);

    cvt_xw_kernel<<<XBLK + WBLK, 256>>>((const float4*)X, Wq, Wk, Wv, (uint4*)xh_ptr);

    dim3 grid(3, M_TOTAL / BM);               // 3 x 197 = 591 CTAs
    qkv_mma_kernel<<<grid, 128, SMEM_DYN>>>(Out);
}